// round 16
// baseline (speedup 1.0000x reference)
#include <cuda_runtime.h>
#include <cuda_fp16.h>
#include <math.h>
#include <stdint.h>

#define Nn   4096
#define DIN  512
#define DOUT 256
#define NH   3
#define BN_EPS 1e-5f
#define MAXK 192          // deg ~ 42 +/- 6.4; 192 is >20 sigma

// GEMM tiling (fp16 mma m16n8k16) — R11/R14 proven config
#define BM 128
#define BNT 128
#define BK 32
#define APAD 40
#define GEMM_BLOCKS 192        // 32 * 2 * 3
#define SCORE_BLOCKS 48        // 3 heads * 16 row-groups of 256
#define TOTAL_BLOCKS (GEMM_BLOCKS + Nn + SCORE_BLOCKS)

// ---------------- scratch (device globals; no runtime allocation) ----------
static __device__ __half g_projh[NH * Nn * DOUT]; // 6.3 MB fp16 proj
static __device__ float g_ssrc[NH * Nn];
static __device__ float g_stgt[NH * Nn];
static __device__ float g_outpre[Nn * DOUT];      // 4 MB
static __device__ float2 g_csr[Nn * MAXK];        // packed (col_bits, val)
static __device__ int   g_deg[Nn];
static __device__ float g_bnsum[DOUT];
static __device__ float g_bnsq [DOUT];

// ---------------- fp16 mma helper -------------------------------------------
__device__ __forceinline__ void mma_fp16(float* d, const uint32_t* a, const uint32_t* b) {
    asm volatile(
        "mma.sync.aligned.m16n8k16.row.col.f32.f16.f16.f32 "
        "{%0,%1,%2,%3}, {%4,%5,%6,%7}, {%8,%9}, {%0,%1,%2,%3};"
        : "+f"(d[0]), "+f"(d[1]), "+f"(d[2]), "+f"(d[3])
        : "r"(a[0]), "r"(a[1]), "r"(a[2]), "r"(a[3]),
          "r"(b[0]), "r"(b[1]));
}

// ---------------- 1) FUSED: fp16 GEMM + CSR-build + SCORE blocks ------------
// blockIdx.x in [0, GEMM_BLOCKS)                : 128x128 proj tile (tensor)
// blockIdx.x in [GEMM_BLOCKS, GEMM_BLOCKS+Nn)   : CSR scan (DRAM stream)
// blockIdx.x >= GEMM_BLOCKS+Nn                  : scores s = F (W s_vec), fp32
__global__ __launch_bounds__(256) void fused_gemm_csr(
    const float* __restrict__ F,    // [Nn, DIN]
    const float* __restrict__ W,    // [NH, DIN, DOUT]
    const float* __restrict__ adj,  // [Nn, Nn]
    const float* __restrict__ Ssrc, // [NH, DOUT]
    const float* __restrict__ Stgt) // [NH, DOUT]
{
    __shared__ __half As [2][BM][APAD];
    __shared__ __half Bst[2][BNT][APAD];
    __shared__ float  s_vec[2][DOUT];   // score vectors (score path)
    __shared__ float  s_u  [2][DIN];    // u = W^T-applied score vecs

    const int bx  = blockIdx.x;
    const int tid = threadIdx.x;

    if (bx >= GEMM_BLOCKS + Nn) {
        // ---------------- SCORE path: s_src/s_tgt = F . (W[h] . vec) -------
        const int bi = bx - GEMM_BLOCKS - Nn;   // 0..47
        const int h  = bi / 16;
        const int rg = bi % 16;
        const int wp = tid >> 5;
        const int ln = tid & 31;

        if (tid < DOUT) {
            s_vec[0][tid] = Ssrc[h * DOUT + tid];
            s_vec[1][tid] = Stgt[h * DOUT + tid];
        }
        __syncthreads();

        // u[vec][k] = sum_c W[h,k,c] * vec[c]   (warp-per-output)
        for (int o = wp; o < 2 * DIN; o += 8) {
            int vec = o >> 9;           // 0/1
            int k   = o & (DIN - 1);
            const float* wrow = &W[((size_t)h * DIN + k) * DOUT];
            float s = 0.f;
#pragma unroll 2
            for (int c = ln; c < DOUT; c += 32)
                s = fmaf(wrow[c], s_vec[vec][c], s);
#pragma unroll
            for (int sh = 16; sh > 0; sh >>= 1)
                s += __shfl_xor_sync(0xffffffffu, s, sh);
            if (ln == 0) s_u[vec][k] = s;
        }
        __syncthreads();

        // scores for rows [rg*256, rg*256+256): warp-per-row
        const int r0 = rg * 256;
        for (int rr = wp; rr < 256; rr += 8) {
            const int n = r0 + rr;
            const float4* frow = (const float4*)&F[(size_t)n * DIN];
            float a = 0.f, b = 0.f;
#pragma unroll
            for (int c4 = ln; c4 < DIN / 4; c4 += 32) {
                float4 f = frow[c4];
                int c = c4 * 4;
                a = fmaf(f.x, s_u[0][c], a); a = fmaf(f.y, s_u[0][c+1], a);
                a = fmaf(f.z, s_u[0][c+2], a); a = fmaf(f.w, s_u[0][c+3], a);
                b = fmaf(f.x, s_u[1][c], b); b = fmaf(f.y, s_u[1][c+1], b);
                b = fmaf(f.z, s_u[1][c+2], b); b = fmaf(f.w, s_u[1][c+3], b);
            }
#pragma unroll
            for (int sh = 16; sh > 0; sh >>= 1) {
                a += __shfl_xor_sync(0xffffffffu, a, sh);
                b += __shfl_xor_sync(0xffffffffu, b, sh);
            }
            if (ln == 0) {
                g_ssrc[h * Nn + n] = a;
                g_stgt[h * Nn + n] = b;
            }
        }
        return;
    }

    if (bx >= GEMM_BLOCKS) {
        // ---------------- CSR path (batched loads, packed writes) ----------
        const int i = bx - GEMM_BLOCKS;
        __shared__ int s_cnt;
        if (tid == 0) s_cnt = 0;
        if (i == 0) { g_bnsum[tid] = 0.f; g_bnsq[tid] = 0.f; }
        __syncthreads();

        const float4* arow = (const float4*)(adj + (size_t)i * Nn);
        float2* csrp = g_csr + (size_t)i * MAXK;

        float4 a4[4];
#pragma unroll
        for (int q4 = 0; q4 < 4; q4++)
            a4[q4] = arow[q4 * 256 + tid];

#pragma unroll
        for (int q4 = 0; q4 < 4; q4++) {
            int jb = (q4 * 256 + tid) * 4;
#pragma unroll
            for (int u = 0; u < 4; u++) {
                float a = (u == 0) ? a4[q4].x : (u == 1) ? a4[q4].y
                        : (u == 2) ? a4[q4].z : a4[q4].w;
                if (a != 0.f) {
                    int p = atomicAdd(&s_cnt, 1);
                    if (p < MAXK) {
                        float2 e; e.x = __int_as_float(jb + u); e.y = a;
                        csrp[p] = e;
                    }
                }
            }
        }
        __syncthreads();
        if (tid == 0) g_deg[i] = min(s_cnt, MAXK);
        return;
    }

    // ---------------- GEMM path: 128x128 tile ----------------
    const int h   = bx / 64;
    const int rem = bx % 64;
    const int m0  = (rem % 32) * BM;
    const int n0  = (rem / 32) * BNT;
    const int warp = tid >> 5;
    const int lane = tid & 31;
    const int g  = lane >> 2;
    const int qd = lane & 3;
    const int wm = warp & 3;
    const int wn = warp >> 2;

    const int ar  = tid >> 2;
    const int af4 = tid & 3;
    const int bk  = tid >> 3;
    const int bf4 = tid & 7;

    float acc[2][8][4];
#pragma unroll
    for (int mt = 0; mt < 2; mt++)
#pragma unroll
        for (int nt = 0; nt < 8; nt++)
#pragma unroll
            for (int v = 0; v < 4; v++) acc[mt][nt][v] = 0.f;

    float4 ra[2][2], rb[4];

#define LDG_TILE(k0)                                                               \
    do {                                                                           \
        _Pragma("unroll")                                                          \
        for (int p = 0; p < 2; p++)                                                \
            _Pragma("unroll")                                                      \
            for (int pp = 0; pp < 2; pp++)                                         \
                ra[p][pp] = *(const float4*)&F[(size_t)(m0 + ar + 64 * p) * DIN    \
                                               + (k0) + (af4 + 4 * pp) * 4];       \
        _Pragma("unroll")                                                          \
        for (int qq = 0; qq < 4; qq++)                                             \
            rb[qq] = *(const float4*)&W[((size_t)h * DIN + (k0) + bk) * DOUT       \
                                        + n0 + (bf4 + 8 * qq) * 4];                \
    } while (0)

#define STS_TILE(buf)                                                              \
    do {                                                                           \
        _Pragma("unroll")                                                          \
        for (int p = 0; p < 2; p++)                                                \
            _Pragma("unroll")                                                      \
            for (int pp = 0; pp < 2; pp++) {                                       \
                __half2 h0 = __floats2half2_rn(ra[p][pp].x, ra[p][pp].y);          \
                __half2 h1 = __floats2half2_rn(ra[p][pp].z, ra[p][pp].w);          \
                __half* dst = &As[buf][ar + 64 * p][(af4 + 4 * pp) * 4];           \
                *(__half2*)&dst[0] = h0;                                           \
                *(__half2*)&dst[2] = h1;                                           \
            }                                                                      \
        _Pragma("unroll")                                                          \
        for (int qq = 0; qq < 4; qq++) {                                           \
            int n = (bf4 + 8 * qq) * 4;                                            \
            Bst[buf][n + 0][bk] = __float2half_rn(rb[qq].x);                       \
            Bst[buf][n + 1][bk] = __float2half_rn(rb[qq].y);                       \
            Bst[buf][n + 2][bk] = __float2half_rn(rb[qq].z);                       \
            Bst[buf][n + 3][bk] = __float2half_rn(rb[qq].w);                       \
        }                                                                          \
    } while (0)

#define MMA_STEP(buf)                                                              \
    do {                                                                           \
        _Pragma("unroll")                                                          \
        for (int ks = 0; ks < 2; ks++) {                                           \
            const int kb = ks * 16;                                                \
            uint32_t af[2][4];                                                     \
            _Pragma("unroll")                                                      \
            for (int mt = 0; mt < 2; mt++) {                                       \
                const int r = wm * 32 + mt * 16 + g;                               \
                af[mt][0] = *(const uint32_t*)&As[buf][r    ][kb + 2 * qd    ];    \
                af[mt][1] = *(const uint32_t*)&As[buf][r + 8][kb + 2 * qd    ];    \
                af[mt][2] = *(const uint32_t*)&As[buf][r    ][kb + 2 * qd + 8];    \
                af[mt][3] = *(const uint32_t*)&As[buf][r + 8][kb + 2 * qd + 8];    \
            }                                                                      \
            uint32_t bf[8][2];                                                     \
            _Pragma("unroll")                                                      \
            for (int nt = 0; nt < 8; nt++) {                                       \
                const int c = wn * 64 + nt * 8 + g;                                \
                bf[nt][0] = *(const uint32_t*)&Bst[buf][c][kb + 2 * qd    ];       \
                bf[nt][1] = *(const uint32_t*)&Bst[buf][c][kb + 2 * qd + 8];       \
            }                                                                      \
            _Pragma("unroll")                                                      \
            for (int mt = 0; mt < 2; mt++)                                         \
                _Pragma("unroll")                                                  \
                for (int nt = 0; nt < 8; nt++)                                     \
                    mma_fp16(acc[mt][nt], af[mt], bf[nt]);                         \
        }                                                                          \
    } while (0)

    LDG_TILE(0);
    STS_TILE(0);
    __syncthreads();

    int buf = 0;
    const int nIter = DIN / BK;   // 16
    for (int it = 0; it < nIter; it++) {
        if (it + 1 < nIter) LDG_TILE((it + 1) * BK);
        MMA_STEP(buf);
        if (it + 1 < nIter) {
            STS_TILE(buf ^ 1);
            __syncthreads();
            buf ^= 1;
        }
    }

#pragma unroll
    for (int mt = 0; mt < 2; mt++) {
        const int r = m0 + wm * 32 + mt * 16 + g;
#pragma unroll
        for (int nt = 0; nt < 8; nt++) {
            const int c = n0 + wn * 64 + nt * 8 + qd * 2;
            __half2 v0 = __floats2half2_rn(acc[mt][nt][0], acc[mt][nt][1]);
            __half2 v1 = __floats2half2_rn(acc[mt][nt][2], acc[mt][nt][3]);
            *(__half2*)&g_projh[((size_t)h * Nn + r    ) * DOUT + c] = v0;
            *(__half2*)&g_projh[((size_t)h * Nn + r + 8) * DOUT + c] = v1;
        }
    }
#undef LDG_TILE
#undef STS_TILE
#undef MMA_STEP
}

// ---------------- 2) warp-per-(row,head) attention (fp16 gather + FFMA2) ---
__global__ __launch_bounds__(384) void attn2(const float* __restrict__ bias) {
    __shared__ float s_acc[NH][4][DOUT];   // 12 KB
    __shared__ float s_bn [DOUT];
    __shared__ float s_bnq[DOUT];

    const int tid  = threadIdx.x;
    const int warp = tid >> 5;        // 0..11
    const int lane = tid & 31;
    const int rl   = warp & 3;        // row-local 0..3
    const int h    = warp >> 2;       // head 0..2
    const int i    = blockIdx.x * 4 + rl;

    if (tid < DOUT) { s_bn[tid] = 0.f; s_bnq[tid] = 0.f; }

    const int deg = g_deg[i];
    const float2* __restrict__ csrp = g_csr + (size_t)i * MAXK;
    const float srci = g_ssrc[h * Nn + i];
    const float* __restrict__ stgt = g_stgt + h * Nn;

    float wv[6];
    int   jv[6];
    float mx = -3.4e38f;
#pragma unroll
    for (int t = 0; t < 6; t++) {
        int k = lane + 32 * t;
        if (k < deg) {
            float2 e = csrp[k];
            int j = __float_as_int(e.x);
            float x = srci + stgt[j];
            float l = (x > 0.f) ? x : 0.2f * x;
            float w = l + e.y;
            wv[t] = w; jv[t] = j;
            mx = fmaxf(mx, w);
        } else { wv[t] = -3.4e38f; jv[t] = 0; }
    }
#pragma unroll
    for (int s = 16; s > 0; s >>= 1)
        mx = fmaxf(mx, __shfl_xor_sync(0xffffffffu, mx, s));

    float sm = 0.f;
#pragma unroll
    for (int t = 0; t < 6; t++) {
        int k = lane + 32 * t;
        float e = (k < deg) ? __expf(wv[t] - mx) : 0.f;
        wv[t] = e;
        sm += e;
    }
#pragma unroll
    for (int s = 16; s > 0; s >>= 1)
        sm += __shfl_xor_sync(0xffffffffu, sm, s);
    const float inv = 1.f / sm;
#pragma unroll
    for (int t = 0; t < 6; t++) wv[t] *= inv;   // padded lanes carry 0

    const __half* __restrict__ base = g_projh + (size_t)h * Nn * DOUT;
    unsigned long long a01 = 0ull, a23 = 0ull, a45 = 0ull, a67 = 0ull;

#define CVT2(P, R)                                                               \
    asm("{.reg .b16 lo, hi;\n\t"                                                 \
        " .reg .f32 x, y;\n\t"                                                   \
        " mov.b32 {lo, hi}, %1;\n\t"                                             \
        " cvt.f32.f16 x, lo;\n\t"                                                \
        " cvt.f32.f16 y, hi;\n\t"                                                \
        " mov.b64 %0, {x, y};}"                                                  \
        : "=l"(P) : "r"(R))

#define HACC(WK, RAW)                                                            \
    do {                                                                         \
        unsigned long long _w2, _p;                                              \
        asm("mov.b64 %0, {%1, %1};" : "=l"(_w2) : "f"(WK));                      \
        CVT2(_p, (RAW).x);                                                       \
        asm("fma.rn.f32x2 %0, %1, %2, %0;" : "+l"(a01) : "l"(_w2), "l"(_p));     \
        CVT2(_p, (RAW).y);                                                       \
        asm("fma.rn.f32x2 %0, %1, %2, %0;" : "+l"(a23) : "l"(_w2), "l"(_p));     \
        CVT2(_p, (RAW).z);                                                       \
        asm("fma.rn.f32x2 %0, %1, %2, %0;" : "+l"(a45) : "l"(_w2), "l"(_p));     \
        CVT2(_p, (RAW).w);                                                       \
        asm("fma.rn.f32x2 %0, %1, %2, %0;" : "+l"(a67) : "l"(_w2), "l"(_p));     \
    } while (0)

#pragma unroll
    for (int t = 0; t < 6; t++) {
        int k0 = 32 * t;
        if (k0 >= deg) break;
        int lim = min(32, deg - k0);
        int p4  = (lim + 3) & ~3;
        float wcur = wv[t];
        int   jcur = jv[t];
        for (int s = 0; s < p4; s += 4) {
            float wk0 = __shfl_sync(0xffffffffu, wcur, s);
            int   jk0 = __shfl_sync(0xffffffffu, jcur, s);
            float wk1 = __shfl_sync(0xffffffffu, wcur, s + 1);
            int   jk1 = __shfl_sync(0xffffffffu, jcur, s + 1);
            float wk2 = __shfl_sync(0xffffffffu, wcur, s + 2);
            int   jk2 = __shfl_sync(0xffffffffu, jcur, s + 2);
            float wk3 = __shfl_sync(0xffffffffu, wcur, s + 3);
            int   jk3 = __shfl_sync(0xffffffffu, jcur, s + 3);
            uint4 r0 = *(const uint4*)&base[(size_t)jk0 * DOUT + lane * 8];
            uint4 r1 = *(const uint4*)&base[(size_t)jk1 * DOUT + lane * 8];
            uint4 r2 = *(const uint4*)&base[(size_t)jk2 * DOUT + lane * 8];
            uint4 r3 = *(const uint4*)&base[(size_t)jk3 * DOUT + lane * 8];
            HACC(wk0, r0);
            HACC(wk1, r1);
            HACC(wk2, r2);
            HACC(wk3, r3);
        }
    }
#undef HACC
#undef CVT2

    float acc[8];
    asm("mov.b64 {%0, %1}, %2;" : "=f"(acc[0]), "=f"(acc[1]) : "l"(a01));
    asm("mov.b64 {%0, %1}, %2;" : "=f"(acc[2]), "=f"(acc[3]) : "l"(a23));
    asm("mov.b64 {%0, %1}, %2;" : "=f"(acc[4]), "=f"(acc[5]) : "l"(a45));
    asm("mov.b64 {%0, %1}, %2;" : "=f"(acc[6]), "=f"(acc[7]) : "l"(a67));

    float4* sp = (float4*)&s_acc[h][rl][lane * 8];
    float4 w0; w0.x = acc[0]; w0.y = acc[1]; w0.z = acc[2]; w0.w = acc[3];
    float4 w1; w1.x = acc[4]; w1.y = acc[5]; w1.z = acc[6]; w1.w = acc[7];
    sp[0] = w0; sp[1] = w1;
    __syncthreads();

    if (warp < 4) {
        const int io = blockIdx.x * 4 + warp;
        const float4* bp = (const float4*)&bias[lane * 8];
        float4 b0 = bp[0], b1 = bp[1];
        float o[8];
#pragma unroll
        for (int v = 0; v < 8; v++) {
            int c = lane * 8 + v;
            float s3 = s_acc[0][warp][c] + s_acc[1][warp][c] + s_acc[2][warp][c];
            float bb = (v < 4) ? ((v == 0) ? b0.x : (v == 1) ? b0.y : (v == 2) ? b0.z : b0.w)
                               : ((v == 4) ? b1.x : (v == 5) ? b1.y : (v == 6) ? b1.z : b1.w);
            o[v] = s3 * (1.f / 3.f) + bb;
        }
        float4* op = (float4*)&g_outpre[(size_t)io * DOUT + lane * 8];
        float4 q0; q0.x = o[0]; q0.y = o[1]; q0.z = o[2]; q0.w = o[3];
        float4 q1; q1.x = o[4]; q1.y = o[5]; q1.z = o[6]; q1.w = o[7];
        op[0] = q0; op[1] = q1;
#pragma unroll
        for (int v = 0; v < 8; v++) {
            int c = lane * 8 + v;
            atomicAdd(&s_bn [c], o[v]);
            atomicAdd(&s_bnq[c], o[v] * o[v]);
        }
    }
    __syncthreads();

    if (tid < DOUT) {
        atomicAdd(&g_bnsum[tid], s_bn [tid]);
        atomicAdd(&g_bnsq [tid], s_bnq[tid]);
    }
}

// ---------------- 3) batchnorm finalize + apply + relu ---------------------
__global__ __launch_bounds__(256) void bn_apply(
    const float* __restrict__ gamma, const float* __restrict__ beta,
    float* __restrict__ out)
{
    __shared__ float s_scale[DOUT];
    __shared__ float s_shift[DOUT];
    const int tid = threadIdx.x;

    {
        float mu  = g_bnsum[tid] * (1.f / Nn);
        float var = g_bnsq [tid] * (1.f / Nn) - mu * mu;
        float sc  = gamma[tid] * rsqrtf(var + BN_EPS);
        s_scale[tid] = sc;
        s_shift[tid] = beta[tid] - mu * sc;
    }
    __syncthreads();

    size_t idx = (size_t)blockIdx.x * 256 + tid;
    int c = ((int)idx * 4) & (DOUT - 1);
    float4 v = *(const float4*)&g_outpre[idx * 4];
    float4 sc = *(const float4*)&s_scale[c];
    float4 sh = *(const float4*)&s_shift[c];
    float4 r;
    r.x = fmaxf(v.x * sc.x + sh.x, 0.f);
    r.y = fmaxf(v.y * sc.y + sh.y, 0.f);
    r.z = fmaxf(v.z * sc.z + sh.z, 0.f);
    r.w = fmaxf(v.w * sc.w + sh.w, 0.f);
    *(float4*)&out[idx * 4] = r;
}

// ---------------- launch ----------------------------------------------------
extern "C" void kernel_launch(void* const* d_in, const int* in_sizes, int n_in,
                              void* d_out, int out_size)
{
    const float* features  = (const float*)d_in[0]; // [4096,512]
    const float* adj       = (const float*)d_in[1]; // [4096,4096]
    const float* weight    = (const float*)d_in[2]; // [3,512,256]
    const float* bias      = (const float*)d_in[3]; // [256]
    const float* score_src = (const float*)d_in[4]; // [3,256,1]
    const float* score_tgt = (const float*)d_in[5]; // [3,256,1]
    const float* bn_gamma  = (const float*)d_in[6]; // [256]
    const float* bn_beta   = (const float*)d_in[7]; // [256]
    float* out = (float*)d_out;                     // [4096,256]

    fused_gemm_csr<<<TOTAL_BLOCKS, 256>>>(features, weight, adj,
                                          score_src, score_tgt);

    attn2<<<Nn / 4, 384>>>(bias);

    bn_apply<<<(Nn * DOUT / 4) / 256, 256>>>(bn_gamma, bn_beta, out);
}

// round 17
// speedup vs baseline: 2.6105x; 2.6105x over previous
#include <cuda_runtime.h>
#include <cuda_fp16.h>
#include <math.h>
#include <stdint.h>

#define Nn   4096
#define DIN  512
#define DOUT 256
#define NH   3
#define BN_EPS 1e-5f
#define MAXK 192          // deg ~ 42 +/- 6.4; 192 is >20 sigma

// GEMM tiling (fp16 mma m16n8k16) — R11/R14 proven config
#define BM 128
#define BNT 128
#define BK 32
#define APAD 40
#define GEMM_BLOCKS 192   // 32 * 2 * 3

// ---------------- scratch (device globals; no runtime allocation) ----------
static __device__ __half g_projh[NH * Nn * DOUT]; // 6.3 MB fp16 proj
static __device__ float g_ssrc[NH * Nn];
static __device__ float g_stgt[NH * Nn];
static __device__ float g_outpre[Nn * DOUT];      // 4 MB
static __device__ float2 g_csr[Nn * MAXK];        // packed (col_bits, val)
static __device__ int   g_deg[Nn];
static __device__ float g_bnsum[DOUT];
static __device__ float g_bnsq [DOUT];

// ---------------- fp16 mma helper -------------------------------------------
__device__ __forceinline__ void mma_fp16(float* d, const uint32_t* a, const uint32_t* b) {
    asm volatile(
        "mma.sync.aligned.m16n8k16.row.col.f32.f16.f16.f32 "
        "{%0,%1,%2,%3}, {%4,%5,%6,%7}, {%8,%9}, {%0,%1,%2,%3};"
        : "+f"(d[0]), "+f"(d[1]), "+f"(d[2]), "+f"(d[3])
        : "r"(a[0]), "r"(a[1]), "r"(a[2]), "r"(a[3]),
          "r"(b[0]), "r"(b[1]));
}

// ---------------- 1) FUSED: fp16 GEMM blocks + CSR-build blocks -------------
__global__ __launch_bounds__(256) void fused_gemm_csr(
    const float* __restrict__ F,    // [Nn, DIN]
    const float* __restrict__ W,    // [NH, DIN, DOUT]
    const float* __restrict__ adj)  // [Nn, Nn]
{
    __shared__ __half As [2][BM][APAD];
    __shared__ __half Bst[2][BNT][APAD];

    const int bx  = blockIdx.x;
    const int tid = threadIdx.x;

    if (bx >= GEMM_BLOCKS) {
        // ---------------- CSR path (batched loads, packed writes) ----------
        const int i = bx - GEMM_BLOCKS;
        __shared__ int s_cnt;
        if (tid == 0) s_cnt = 0;
        if (i == 0) { g_bnsum[tid] = 0.f; g_bnsq[tid] = 0.f; }
        __syncthreads();

        const float4* arow = (const float4*)(adj + (size_t)i * Nn);
        float2* csrp = g_csr + (size_t)i * MAXK;

        float4 a4[4];
#pragma unroll
        for (int q4 = 0; q4 < 4; q4++)
            a4[q4] = arow[q4 * 256 + tid];

#pragma unroll
        for (int q4 = 0; q4 < 4; q4++) {
            int jb = (q4 * 256 + tid) * 4;
#pragma unroll
            for (int u = 0; u < 4; u++) {
                float a = (u == 0) ? a4[q4].x : (u == 1) ? a4[q4].y
                        : (u == 2) ? a4[q4].z : a4[q4].w;
                if (a != 0.f) {
                    int p = atomicAdd(&s_cnt, 1);
                    if (p < MAXK) {
                        float2 e; e.x = __int_as_float(jb + u); e.y = a;
                        csrp[p] = e;
                    }
                }
            }
        }
        __syncthreads();
        if (tid == 0) g_deg[i] = min(s_cnt, MAXK);
        return;
    }

    // ---------------- GEMM path: 128x128 tile ----------------
    const int h   = bx / 64;
    const int rem = bx % 64;
    const int m0  = (rem % 32) * BM;
    const int n0  = (rem / 32) * BNT;
    const int warp = tid >> 5;
    const int lane = tid & 31;
    const int g  = lane >> 2;
    const int qd = lane & 3;
    const int wm = warp & 3;
    const int wn = warp >> 2;

    const int ar  = tid >> 2;
    const int af4 = tid & 3;
    const int bk  = tid >> 3;
    const int bf4 = tid & 7;

    float acc[2][8][4];
#pragma unroll
    for (int mt = 0; mt < 2; mt++)
#pragma unroll
        for (int nt = 0; nt < 8; nt++)
#pragma unroll
            for (int v = 0; v < 4; v++) acc[mt][nt][v] = 0.f;

    float4 ra[2][2], rb[4];

#define LDG_TILE(k0)                                                               \
    do {                                                                           \
        _Pragma("unroll")                                                          \
        for (int p = 0; p < 2; p++)                                                \
            _Pragma("unroll")                                                      \
            for (int pp = 0; pp < 2; pp++)                                         \
                ra[p][pp] = *(const float4*)&F[(size_t)(m0 + ar + 64 * p) * DIN    \
                                               + (k0) + (af4 + 4 * pp) * 4];       \
        _Pragma("unroll")                                                          \
        for (int qq = 0; qq < 4; qq++)                                             \
            rb[qq] = *(const float4*)&W[((size_t)h * DIN + (k0) + bk) * DOUT       \
                                        + n0 + (bf4 + 8 * qq) * 4];                \
    } while (0)

#define STS_TILE(buf)                                                              \
    do {                                                                           \
        _Pragma("unroll")                                                          \
        for (int p = 0; p < 2; p++)                                                \
            _Pragma("unroll")                                                      \
            for (int pp = 0; pp < 2; pp++) {                                       \
                __half2 h0 = __floats2half2_rn(ra[p][pp].x, ra[p][pp].y);          \
                __half2 h1 = __floats2half2_rn(ra[p][pp].z, ra[p][pp].w);          \
                __half* dst = &As[buf][ar + 64 * p][(af4 + 4 * pp) * 4];           \
                *(__half2*)&dst[0] = h0;                                           \
                *(__half2*)&dst[2] = h1;                                           \
            }                                                                      \
        _Pragma("unroll")                                                          \
        for (int qq = 0; qq < 4; qq++) {                                           \
            int n = (bf4 + 8 * qq) * 4;                                            \
            Bst[buf][n + 0][bk] = __float2half_rn(rb[qq].x);                       \
            Bst[buf][n + 1][bk] = __float2half_rn(rb[qq].y);                       \
            Bst[buf][n + 2][bk] = __float2half_rn(rb[qq].z);                       \
            Bst[buf][n + 3][bk] = __float2half_rn(rb[qq].w);                       \
        }                                                                          \
    } while (0)

#define MMA_STEP(buf)                                                              \
    do {                                                                           \
        _Pragma("unroll")                                                          \
        for (int ks = 0; ks < 2; ks++) {                                           \
            const int kb = ks * 16;                                                \
            uint32_t af[2][4];                                                     \
            _Pragma("unroll")                                                      \
            for (int mt = 0; mt < 2; mt++) {                                       \
                const int r = wm * 32 + mt * 16 + g;                               \
                af[mt][0] = *(const uint32_t*)&As[buf][r    ][kb + 2 * qd    ];    \
                af[mt][1] = *(const uint32_t*)&As[buf][r + 8][kb + 2 * qd    ];    \
                af[mt][2] = *(const uint32_t*)&As[buf][r    ][kb + 2 * qd + 8];    \
                af[mt][3] = *(const uint32_t*)&As[buf][r + 8][kb + 2 * qd + 8];    \
            }                                                                      \
            uint32_t bf[8][2];                                                     \
            _Pragma("unroll")                                                      \
            for (int nt = 0; nt < 8; nt++) {                                       \
                const int c = wn * 64 + nt * 8 + g;                                \
                bf[nt][0] = *(const uint32_t*)&Bst[buf][c][kb + 2 * qd    ];       \
                bf[nt][1] = *(const uint32_t*)&Bst[buf][c][kb + 2 * qd + 8];       \
            }                                                                      \
            _Pragma("unroll")                                                      \
            for (int mt = 0; mt < 2; mt++)                                         \
                _Pragma("unroll")                                                  \
                for (int nt = 0; nt < 8; nt++)                                     \
                    mma_fp16(acc[mt][nt], af[mt], bf[nt]);                         \
        }                                                                          \
    } while (0)

    LDG_TILE(0);
    STS_TILE(0);
    __syncthreads();

    int buf = 0;
    const int nIter = DIN / BK;   // 16
    for (int it = 0; it < nIter; it++) {
        if (it + 1 < nIter) LDG_TILE((it + 1) * BK);
        MMA_STEP(buf);
        if (it + 1 < nIter) {
            STS_TILE(buf ^ 1);
            __syncthreads();
            buf ^= 1;
        }
    }

#pragma unroll
    for (int mt = 0; mt < 2; mt++) {
        const int r = m0 + wm * 32 + mt * 16 + g;
#pragma unroll
        for (int nt = 0; nt < 8; nt++) {
            const int c = n0 + wn * 64 + nt * 8 + qd * 2;
            __half2 v0 = __floats2half2_rn(acc[mt][nt][0], acc[mt][nt][1]);
            __half2 v1 = __floats2half2_rn(acc[mt][nt][2], acc[mt][nt][3]);
            *(__half2*)&g_projh[((size_t)h * Nn + r    ) * DOUT + c] = v0;
            *(__half2*)&g_projh[((size_t)h * Nn + r + 8) * DOUT + c] = v1;
        }
    }
#undef LDG_TILE
#undef STS_TILE
#undef MMA_STEP
}

// ---------------- 2) attention logit scalars --------------------------------
__global__ __launch_bounds__(256) void score_kernel(
    const float* __restrict__ Ssrc,   // [NH, DOUT]
    const float* __restrict__ Stgt)
{
    int gw   = (blockIdx.x * blockDim.x + threadIdx.x) >> 5;
    int lane = threadIdx.x & 31;
    if (gw >= NH * Nn) return;
    int h = gw / Nn, n = gw % Nn;
    const __half* row = g_projh + ((size_t)h * Nn + n) * DOUT;

    uint4 raw = *(const uint4*)&row[lane * 8];
    float2 p0 = __half22float2(*(__half2*)&raw.x);
    float2 p1 = __half22float2(*(__half2*)&raw.y);
    float2 p2 = __half22float2(*(__half2*)&raw.z);
    float2 p3 = __half22float2(*(__half2*)&raw.w);

    const float4* sp = (const float4*)&Ssrc[h * DOUT + lane * 8];
    const float4* tp = (const float4*)&Stgt[h * DOUT + lane * 8];
    float4 s0 = sp[0], s1 = sp[1];
    float4 t0 = tp[0], t1 = tp[1];

    float a = p0.x * s0.x + p0.y * s0.y + p1.x * s0.z + p1.y * s0.w
            + p2.x * s1.x + p2.y * s1.y + p3.x * s1.z + p3.y * s1.w;
    float b = p0.x * t0.x + p0.y * t0.y + p1.x * t0.z + p1.y * t0.w
            + p2.x * t1.x + p2.y * t1.y + p3.x * t1.z + p3.y * t1.w;
#pragma unroll
    for (int s = 16; s > 0; s >>= 1) {
        a += __shfl_xor_sync(0xffffffffu, a, s);
        b += __shfl_xor_sync(0xffffffffu, b, s);
    }
    if (lane == 0) {
        g_ssrc[h * Nn + n] = a;
        g_stgt[h * Nn + n] = b;
    }
}

// ---------------- 3) warp-per-(row,head) attention (fp16 gather + FFMA2) ---
__global__ __launch_bounds__(384) void attn2(const float* __restrict__ bias) {
    __shared__ float s_acc[NH][4][DOUT];   // 12 KB
    __shared__ float s_bn [DOUT];
    __shared__ float s_bnq[DOUT];

    const int tid  = threadIdx.x;
    const int warp = tid >> 5;        // 0..11
    const int lane = tid & 31;
    const int rl   = warp & 3;        // row-local 0..3
    const int h    = warp >> 2;       // head 0..2
    const int i    = blockIdx.x * 4 + rl;

    if (tid < DOUT) { s_bn[tid] = 0.f; s_bnq[tid] = 0.f; }

    const int deg = g_deg[i];
    const float2* __restrict__ csrp = g_csr + (size_t)i * MAXK;
    const float srci = g_ssrc[h * Nn + i];
    const float* __restrict__ stgt = g_stgt + h * Nn;

    float wv[6];
    int   jv[6];
    float mx = -3.4e38f;
#pragma unroll
    for (int t = 0; t < 6; t++) {
        int k = lane + 32 * t;
        if (k < deg) {
            float2 e = csrp[k];
            int j = __float_as_int(e.x);
            float x = srci + stgt[j];
            float l = (x > 0.f) ? x : 0.2f * x;
            float w = l + e.y;
            wv[t] = w; jv[t] = j;
            mx = fmaxf(mx, w);
        } else { wv[t] = -3.4e38f; jv[t] = 0; }
    }
#pragma unroll
    for (int s = 16; s > 0; s >>= 1)
        mx = fmaxf(mx, __shfl_xor_sync(0xffffffffu, mx, s));

    float sm = 0.f;
#pragma unroll
    for (int t = 0; t < 6; t++) {
        int k = lane + 32 * t;
        float e = (k < deg) ? __expf(wv[t] - mx) : 0.f;
        wv[t] = e;
        sm += e;
    }
#pragma unroll
    for (int s = 16; s > 0; s >>= 1)
        sm += __shfl_xor_sync(0xffffffffu, sm, s);
    const float inv = 1.f / sm;
#pragma unroll
    for (int t = 0; t < 6; t++) wv[t] *= inv;   // padded lanes carry 0

    const __half* __restrict__ base = g_projh + (size_t)h * Nn * DOUT;
    unsigned long long a01 = 0ull, a23 = 0ull, a45 = 0ull, a67 = 0ull;

#define CVT2(P, R)                                                               \
    asm("{.reg .b16 lo, hi;\n\t"                                                 \
        " .reg .f32 x, y;\n\t"                                                   \
        " mov.b32 {lo, hi}, %1;\n\t"                                             \
        " cvt.f32.f16 x, lo;\n\t"                                                \
        " cvt.f32.f16 y, hi;\n\t"                                                \
        " mov.b64 %0, {x, y};}"                                                  \
        : "=l"(P) : "r"(R))

#define HACC(WK, RAW)                                                            \
    do {                                                                         \
        unsigned long long _w2, _p;                                              \
        asm("mov.b64 %0, {%1, %1};" : "=l"(_w2) : "f"(WK));                      \
        CVT2(_p, (RAW).x);                                                       \
        asm("fma.rn.f32x2 %0, %1, %2, %0;" : "+l"(a01) : "l"(_w2), "l"(_p));     \
        CVT2(_p, (RAW).y);                                                       \
        asm("fma.rn.f32x2 %0, %1, %2, %0;" : "+l"(a23) : "l"(_w2), "l"(_p));     \
        CVT2(_p, (RAW).z);                                                       \
        asm("fma.rn.f32x2 %0, %1, %2, %0;" : "+l"(a45) : "l"(_w2), "l"(_p));     \
        CVT2(_p, (RAW).w);                                                       \
        asm("fma.rn.f32x2 %0, %1, %2, %0;" : "+l"(a67) : "l"(_w2), "l"(_p));     \
    } while (0)

#pragma unroll
    for (int t = 0; t < 6; t++) {
        int k0 = 32 * t;
        if (k0 >= deg) break;
        int lim = min(32, deg - k0);
        int p4  = (lim + 3) & ~3;
        float wcur = wv[t];
        int   jcur = jv[t];
        for (int s = 0; s < p4; s += 4) {
            float wk0 = __shfl_sync(0xffffffffu, wcur, s);
            int   jk0 = __shfl_sync(0xffffffffu, jcur, s);
            float wk1 = __shfl_sync(0xffffffffu, wcur, s + 1);
            int   jk1 = __shfl_sync(0xffffffffu, jcur, s + 1);
            float wk2 = __shfl_sync(0xffffffffu, wcur, s + 2);
            int   jk2 = __shfl_sync(0xffffffffu, jcur, s + 2);
            float wk3 = __shfl_sync(0xffffffffu, wcur, s + 3);
            int   jk3 = __shfl_sync(0xffffffffu, jcur, s + 3);
            uint4 r0 = *(const uint4*)&base[(size_t)jk0 * DOUT + lane * 8];
            uint4 r1 = *(const uint4*)&base[(size_t)jk1 * DOUT + lane * 8];
            uint4 r2 = *(const uint4*)&base[(size_t)jk2 * DOUT + lane * 8];
            uint4 r3 = *(const uint4*)&base[(size_t)jk3 * DOUT + lane * 8];
            HACC(wk0, r0);
            HACC(wk1, r1);
            HACC(wk2, r2);
            HACC(wk3, r3);
        }
    }
#undef HACC
#undef CVT2

    float acc[8];
    asm("mov.b64 {%0, %1}, %2;" : "=f"(acc[0]), "=f"(acc[1]) : "l"(a01));
    asm("mov.b64 {%0, %1}, %2;" : "=f"(acc[2]), "=f"(acc[3]) : "l"(a23));
    asm("mov.b64 {%0, %1}, %2;" : "=f"(acc[4]), "=f"(acc[5]) : "l"(a45));
    asm("mov.b64 {%0, %1}, %2;" : "=f"(acc[6]), "=f"(acc[7]) : "l"(a67));

    float4* sp = (float4*)&s_acc[h][rl][lane * 8];
    float4 w0; w0.x = acc[0]; w0.y = acc[1]; w0.z = acc[2]; w0.w = acc[3];
    float4 w1; w1.x = acc[4]; w1.y = acc[5]; w1.z = acc[6]; w1.w = acc[7];
    sp[0] = w0; sp[1] = w1;
    __syncthreads();

    if (warp < 4) {
        const int io = blockIdx.x * 4 + warp;
        const float4* bp = (const float4*)&bias[lane * 8];
        float4 b0 = bp[0], b1 = bp[1];
        float o[8];
#pragma unroll
        for (int v = 0; v < 8; v++) {
            int c = lane * 8 + v;
            float s3 = s_acc[0][warp][c] + s_acc[1][warp][c] + s_acc[2][warp][c];
            float bb = (v < 4) ? ((v == 0) ? b0.x : (v == 1) ? b0.y : (v == 2) ? b0.z : b0.w)
                               : ((v == 4) ? b1.x : (v == 5) ? b1.y : (v == 6) ? b1.z : b1.w);
            o[v] = s3 * (1.f / 3.f) + bb;
        }
        float4* op = (float4*)&g_outpre[(size_t)io * DOUT + lane * 8];
        float4 q0; q0.x = o[0]; q0.y = o[1]; q0.z = o[2]; q0.w = o[3];
        float4 q1; q1.x = o[4]; q1.y = o[5]; q1.z = o[6]; q1.w = o[7];
        op[0] = q0; op[1] = q1;
#pragma unroll
        for (int v = 0; v < 8; v++) {
            int c = lane * 8 + v;
            atomicAdd(&s_bn [c], o[v]);
            atomicAdd(&s_bnq[c], o[v] * o[v]);
        }
    }
    __syncthreads();

    if (tid < DOUT) {
        atomicAdd(&g_bnsum[tid], s_bn [tid]);
        atomicAdd(&g_bnsq [tid], s_bnq[tid]);
    }
}

// ---------------- 4) batchnorm finalize + apply + relu ---------------------
__global__ __launch_bounds__(256) void bn_apply(
    const float* __restrict__ gamma, const float* __restrict__ beta,
    float* __restrict__ out)
{
    __shared__ float s_scale[DOUT];
    __shared__ float s_shift[DOUT];
    const int tid = threadIdx.x;

    {
        float mu  = g_bnsum[tid] * (1.f / Nn);
        float var = g_bnsq [tid] * (1.f / Nn) - mu * mu;
        float sc  = gamma[tid] * rsqrtf(var + BN_EPS);
        s_scale[tid] = sc;
        s_shift[tid] = beta[tid] - mu * sc;
    }
    __syncthreads();

    size_t idx = (size_t)blockIdx.x * 256 + tid;
    int c = ((int)idx * 4) & (DOUT - 1);
    float4 v = *(const float4*)&g_outpre[idx * 4];
    float4 sc = *(const float4*)&s_scale[c];
    float4 sh = *(const float4*)&s_shift[c];
    float4 r;
    r.x = fmaxf(v.x * sc.x + sh.x, 0.f);
    r.y = fmaxf(v.y * sc.y + sh.y, 0.f);
    r.z = fmaxf(v.z * sc.z + sh.z, 0.f);
    r.w = fmaxf(v.w * sc.w + sh.w, 0.f);
    *(float4*)&out[idx * 4] = r;
}

// ---------------- launch ----------------------------------------------------
extern "C" void kernel_launch(void* const* d_in, const int* in_sizes, int n_in,
                              void* d_out, int out_size)
{
    const float* features  = (const float*)d_in[0]; // [4096,512]
    const float* adj       = (const float*)d_in[1]; // [4096,4096]
    const float* weight    = (const float*)d_in[2]; // [3,512,256]
    const float* bias      = (const float*)d_in[3]; // [256]
    const float* score_src = (const float*)d_in[4]; // [3,256,1]
    const float* score_tgt = (const float*)d_in[5]; // [3,256,1]
    const float* bn_gamma  = (const float*)d_in[6]; // [256]
    const float* bn_beta   = (const float*)d_in[7]; // [256]
    float* out = (float*)d_out;                     // [4096,256]

    fused_gemm_csr<<<GEMM_BLOCKS + Nn, 256>>>(features, weight, adj);

    score_kernel<<<(NH * Nn) / 8, 256>>>(score_src, score_tgt);

    attn2<<<Nn / 4, 384>>>(bias);

    bn_apply<<<(Nn * DOUT / 4) / 256, 256>>>(bn_gamma, bn_beta, out);
}